// round 6
// baseline (speedup 1.0000x reference)
#include <cuda_runtime.h>

// Problem constants
#define HID     50
#define NG      200
#define IN0     17
#define SDIM    16
#define TSTEPS  128
#define FC1N    25

// Tiling
#define ROWS      64
#define NTHREADS  416     // 13 warps
#define NPAIR     8       // 8 float2 pairs = 16 rows per slot

// Strides (floats)
#define WI_S      17
#define WH_S      51
#define FC1_S     51
#define TSTRIDE   68      // 272B, 16B-aligned rows

// Per-gate weight blocks; block deltas == 16 (mod 32) banks -> half-warp complement
#define GB0       880
#define GBH       2576

typedef unsigned long long ull;

__device__ __forceinline__ ull pack2(float a, float b) {
    ull r; asm("mov.b64 %0,{%1,%2};" : "=l"(r) : "f"(a), "f"(b)); return r;
}
__device__ __forceinline__ float2 unpk(ull v) {
    float2 f; asm("mov.b64 {%0,%1},%2;" : "=f"(f.x), "=f"(f.y) : "l"(v)); return f;
}
__device__ __forceinline__ void fma2(ull& d, ull a, ull b) {
    asm("fma.rn.f32x2 %0,%1,%2,%0;" : "+l"(d) : "l"(a), "l"(b));
}
__device__ __forceinline__ void add2(ull& d, ull a) {
    asm("add.rn.f32x2 %0,%0,%1;" : "+l"(d) : "l"(a));
}
__device__ __forceinline__ float tanh_a(float x) {
    float y; asm("tanh.approx.f32 %0,%1;" : "=f"(y) : "f"(x)); return y;
}
__device__ __forceinline__ float sig_a(float x) {
    return fmaf(tanh_a(0.5f * x), 0.5f, 0.5f);
}

// Shared layout (float offsets)
#define OFF_WIH0   0                       // 4*880  = 3520
#define OFF_WHH0   3520                    // 4*2576 = 10304
#define OFF_WIH1   13824
#define OFF_WHH1   24128
#define OFF_FC1    34432                   // 25*51 = 1275
#define OFF_FC2    35708                   // 25
#define OFF_B0     35734                   // 200
#define OFF_B1     35934                   // 200
#define OFF_BFC1   36134                   // 25
#define OFF_BFC2   36160                   // 2 (+2 pad)
#define OFF_X      36164                   // 17*68 = 1156
#define OFF_H0     37320                   // 2*50*68 = 6800
#define OFF_H1     44120                   // 6800
#define SMEM_FLOATS 50920                  // 203680 bytes

__global__ __launch_bounds__(NTHREADS, 1)
void kozyra_lstm_kernel(const float* __restrict__ features,
                        const float* __restrict__ w_ih0, const float* __restrict__ w_hh0,
                        const float* __restrict__ b0,
                        const float* __restrict__ w_ih1, const float* __restrict__ w_hh1,
                        const float* __restrict__ b1,
                        const float* __restrict__ w_fc1, const float* __restrict__ b_fc1,
                        const float* __restrict__ w_fc2, const float* __restrict__ b_fc2,
                        float* __restrict__ out)
{
    extern __shared__ float sm[];
    float* s_fc1  = sm + OFF_FC1;
    float* s_fc2  = sm + OFF_FC2;
    float* s_b0   = sm + OFF_B0;
    float* s_b1   = sm + OFF_B1;
    float* s_bfc1 = sm + OFF_BFC1;
    float* s_bfc2 = sm + OFF_BFC2;
    float* s_x    = sm + OFF_X;      // [IN0][TSTRIDE]
    float* s_h0b  = sm + OFF_H0;     // 2 x [HID][TSTRIDE]
    float* s_h1b  = sm + OFF_H1;

    const int tid  = threadIdx.x;
    const int brow = blockIdx.x * ROWS;

    // ---- Stage weights: per-gate blocks, order I(0) G(1) F(2) O(3) ----
    for (int idx = tid; idx < NG * IN0; idx += NTHREADS) {
        int row = idx / IN0, k = idx % IN0;
        int gate = row / HID, jj = row % HID;
        int blk = (gate == 0) ? 0 : (gate == 1) ? 2 : (gate == 2) ? 1 : 3;
        sm[OFF_WIH0 + blk * GB0 + jj * WI_S + k] = w_ih0[idx];
    }
    for (int idx = tid; idx < NG * HID; idx += NTHREADS) {
        int row = idx / HID, k = idx % HID;
        int gate = row / HID, jj = row % HID;
        int blk = (gate == 0) ? 0 : (gate == 1) ? 2 : (gate == 2) ? 1 : 3;
        int o = blk * GBH + jj * WH_S + k;
        sm[OFF_WHH0 + o] = w_hh0[idx];
        sm[OFF_WIH1 + o] = w_ih1[idx];
        sm[OFF_WHH1 + o] = w_hh1[idx];
    }
    for (int i = tid; i < FC1N * HID; i += NTHREADS) {
        int n = i / HID, k = i % HID;
        s_fc1[n * FC1_S + k] = w_fc1[i];
    }
    for (int i = tid; i < FC1N; i += NTHREADS) { s_fc2[i] = w_fc2[i]; s_bfc1[i] = b_fc1[i]; }
    for (int i = tid; i < NG;   i += NTHREADS) { s_b0[i] = b0[i]; s_b1[i] = b1[i]; }
    if (tid == 0) s_bfc2[0] = b_fc2[0];

    // ---- Init state + x for t=0 ----
    for (int i = tid; i < 2 * HID * TSTRIDE; i += NTHREADS) { s_h0b[i] = 0.0f; s_h1b[i] = 0.0f; }
    const float* fbase = features + (size_t)brow * (TSTEPS * SDIM);
    for (int i = tid; i < ROWS * SDIM; i += NTHREADS) {
        int r = i >> 4, s = i & 15;
        s_x[s * TSTRIDE + r] = fbase[(size_t)r * (TSTEPS * SDIM) + s];
    }
    if (tid < ROWS) s_x[SDIM * TSTRIDE + tid] = 0.0f;
    __syncthreads();

    // ---- Thread mapping: straddle-free, 16 rows per slot ----
    const int w    = tid >> 5;
    const int lane = tid & 31;
    const int gs   = lane >> 4;          // 0 -> (i,f), 1 -> (g,o)
    const int sub  = lane & 15;
    int rg, j; bool dup = false;
    if (w < 12) { rg = w / 3; j = (w % 3) * 16 + sub; }
    else { int s8 = sub & 7; dup = (sub >= 8); rg = s8 >> 1; j = 48 + (s8 & 1); }
    const int r0 = rg * 16;

    const float* pA_ih0 = sm + OFF_WIH0 + gs * GB0 + j * WI_S;
    const float* pB_ih0 = pA_ih0 + 2 * GB0;
    const float* pA_hh0 = sm + OFF_WHH0 + gs * GBH + j * WH_S;
    const float* pB_hh0 = pA_hh0 + 2 * GBH;
    const float* pA_ih1 = sm + OFF_WIH1 + gs * GBH + j * WH_S;
    const float* pB_ih1 = pA_ih1 + 2 * GBH;
    const float* pA_hh1 = sm + OFF_WHH1 + gs * GBH + j * WH_S;
    const float* pB_hh1 = pA_hh1 + 2 * GBH;

    const float bA0 = s_b0[(gs ? 2 : 0) * HID + j];
    const float bB0 = s_b0[(gs ? 3 : 1) * HID + j];
    const float bA1 = s_b1[(gs ? 2 : 0) * HID + j];
    const float bB1 = s_b1[(gs ? 3 : 1) * HID + j];
    const ull bpA0 = pack2(bA0, bA0), bpB0 = pack2(bB0, bB0);
    const ull bpA1 = pack2(bA1, bA1), bpB1 = pack2(bB1, bB1);

    // Cell state for owned pairs lp=0..3 (pair index 4*gs+lp)
    float cx[2][4], cy[2][4];
    #pragma unroll
    for (int L = 0; L < 2; L++)
        #pragma unroll
        for (int p = 0; p < 4; p++) { cx[L][p] = 0.0f; cy[L][p] = 0.0f; }

    for (int t = 0; t < TSTEPS; t++) {
        const int pb = t & 1;
        float* h0r = s_h0b + pb * (HID * TSTRIDE);
        float* h0w = s_h0b + (pb ^ 1) * (HID * TSTRIDE);
        float* h1r = s_h1b + pb * (HID * TSTRIDE);
        float* h1w = s_h1b + (pb ^ 1) * (HID * TSTRIDE);

        ull a0[NPAIR], a1[NPAIR];

        // ================= Layer 0 =================
        #pragma unroll
        for (int p = 0; p < NPAIR; p++) { a0[p] = bpA0; a1[p] = bpB0; }

        #pragma unroll 4
        for (int k = 0; k < IN0; k++) {
            float wa = pA_ih0[k], wb = pB_ih0[k];
            ull wpa = pack2(wa, wa), wpb = pack2(wb, wb);
            const float* sb = &s_x[k * TSTRIDE + r0];
            ulonglong2 v0 = *(const ulonglong2*)(sb);
            ulonglong2 v1 = *(const ulonglong2*)(sb + 4);
            ulonglong2 v2 = *(const ulonglong2*)(sb + 8);
            ulonglong2 v3 = *(const ulonglong2*)(sb + 12);
            fma2(a0[0], wpa, v0.x); fma2(a0[1], wpa, v0.y);
            fma2(a0[2], wpa, v1.x); fma2(a0[3], wpa, v1.y);
            fma2(a0[4], wpa, v2.x); fma2(a0[5], wpa, v2.y);
            fma2(a0[6], wpa, v3.x); fma2(a0[7], wpa, v3.y);
            fma2(a1[0], wpb, v0.x); fma2(a1[1], wpb, v0.y);
            fma2(a1[2], wpb, v1.x); fma2(a1[3], wpb, v1.y);
            fma2(a1[4], wpb, v2.x); fma2(a1[5], wpb, v2.y);
            fma2(a1[6], wpb, v3.x); fma2(a1[7], wpb, v3.y);
        }
        #pragma unroll 5
        for (int k = 0; k < HID; k++) {
            float wa = pA_hh0[k], wb = pB_hh0[k];
            ull wpa = pack2(wa, wa), wpb = pack2(wb, wb);
            const float* sb = &h0r[k * TSTRIDE + r0];
            ulonglong2 v0 = *(const ulonglong2*)(sb);
            ulonglong2 v1 = *(const ulonglong2*)(sb + 4);
            ulonglong2 v2 = *(const ulonglong2*)(sb + 8);
            ulonglong2 v3 = *(const ulonglong2*)(sb + 12);
            fma2(a0[0], wpa, v0.x); fma2(a0[1], wpa, v0.y);
            fma2(a0[2], wpa, v1.x); fma2(a0[3], wpa, v1.y);
            fma2(a0[4], wpa, v2.x); fma2(a0[5], wpa, v2.y);
            fma2(a0[6], wpa, v3.x); fma2(a0[7], wpa, v3.y);
            fma2(a1[0], wpb, v0.x); fma2(a1[1], wpb, v0.y);
            fma2(a1[2], wpb, v1.x); fma2(a1[3], wpb, v1.y);
            fma2(a1[4], wpb, v2.x); fma2(a1[5], wpb, v2.y);
            fma2(a1[6], wpb, v3.x); fma2(a1[7], wpb, v3.y);
        }

        {   // exchange + nonlinearity, layer 0
            ull sx[8];
            #pragma unroll
            for (int q = 0; q < 4; q++) {
                sx[q]     = gs ? a0[q] : a0[4 + q];
                sx[4 + q] = gs ? a1[q] : a1[4 + q];
            }
            ull rx[8];
            #pragma unroll
            for (int q = 0; q < 8; q++) rx[q] = __shfl_xor_sync(0xffffffffu, sx[q], 16);
            #pragma unroll
            for (int lp = 0; lp < 4; lp++) {
                ull gi = gs ? rx[lp]     : a0[lp];
                ull gf = gs ? rx[4 + lp] : a1[lp];
                ull gg = gs ? a0[4 + lp] : rx[lp];
                ull go = gs ? a1[4 + lp] : rx[4 + lp];
                float2 vi = unpk(gi), vf = unpk(gf), vg = unpk(gg), vo = unpk(go);
                float ncx = sig_a(vf.x) * cx[0][lp] + sig_a(vi.x) * tanh_a(vg.x);
                float ncy = sig_a(vf.y) * cy[0][lp] + sig_a(vi.y) * tanh_a(vg.y);
                cx[0][lp] = ncx; cy[0][lp] = ncy;
                float hx = sig_a(vo.x) * tanh_a(ncx);
                float hy = sig_a(vo.y) * tanh_a(ncy);
                if (!dup)
                    *(float2*)&h0w[j * TSTRIDE + r0 + 2 * (4 * gs + lp)] = make_float2(hx, hy);
            }
        }
        __syncthreads();   // h0 visible

        // ================= Layer 1 =================
        #pragma unroll
        for (int p = 0; p < NPAIR; p++) { a0[p] = bpA1; a1[p] = bpB1; }

        #pragma unroll 5
        for (int k = 0; k < HID; k++) {
            float wa = pA_ih1[k], wb = pB_ih1[k];
            ull wpa = pack2(wa, wa), wpb = pack2(wb, wb);
            const float* sb = &h0w[k * TSTRIDE + r0];
            ulonglong2 v0 = *(const ulonglong2*)(sb);
            ulonglong2 v1 = *(const ulonglong2*)(sb + 4);
            ulonglong2 v2 = *(const ulonglong2*)(sb + 8);
            ulonglong2 v3 = *(const ulonglong2*)(sb + 12);
            fma2(a0[0], wpa, v0.x); fma2(a0[1], wpa, v0.y);
            fma2(a0[2], wpa, v1.x); fma2(a0[3], wpa, v1.y);
            fma2(a0[4], wpa, v2.x); fma2(a0[5], wpa, v2.y);
            fma2(a0[6], wpa, v3.x); fma2(a0[7], wpa, v3.y);
            fma2(a1[0], wpb, v0.x); fma2(a1[1], wpb, v0.y);
            fma2(a1[2], wpb, v1.x); fma2(a1[3], wpb, v1.y);
            fma2(a1[4], wpb, v2.x); fma2(a1[5], wpb, v2.y);
            fma2(a1[6], wpb, v3.x); fma2(a1[7], wpb, v3.y);
        }
        #pragma unroll 5
        for (int k = 0; k < HID; k++) {
            float wa = pA_hh1[k], wb = pB_hh1[k];
            ull wpa = pack2(wa, wa), wpb = pack2(wb, wb);
            const float* sb = &h1r[k * TSTRIDE + r0];
            ulonglong2 v0 = *(const ulonglong2*)(sb);
            ulonglong2 v1 = *(const ulonglong2*)(sb + 4);
            ulonglong2 v2 = *(const ulonglong2*)(sb + 8);
            ulonglong2 v3 = *(const ulonglong2*)(sb + 12);
            fma2(a0[0], wpa, v0.x); fma2(a0[1], wpa, v0.y);
            fma2(a0[2], wpa, v1.x); fma2(a0[3], wpa, v1.y);
            fma2(a0[4], wpa, v2.x); fma2(a0[5], wpa, v2.y);
            fma2(a0[6], wpa, v3.x); fma2(a0[7], wpa, v3.y);
            fma2(a1[0], wpb, v0.x); fma2(a1[1], wpb, v0.y);
            fma2(a1[2], wpb, v1.x); fma2(a1[3], wpb, v1.y);
            fma2(a1[4], wpb, v2.x); fma2(a1[5], wpb, v2.y);
            fma2(a1[6], wpb, v3.x); fma2(a1[7], wpb, v3.y);
        }

        {   // exchange + nonlinearity, layer 1
            ull sx[8];
            #pragma unroll
            for (int q = 0; q < 4; q++) {
                sx[q]     = gs ? a0[q] : a0[4 + q];
                sx[4 + q] = gs ? a1[q] : a1[4 + q];
            }
            ull rx[8];
            #pragma unroll
            for (int q = 0; q < 8; q++) rx[q] = __shfl_xor_sync(0xffffffffu, sx[q], 16);
            #pragma unroll
            for (int lp = 0; lp < 4; lp++) {
                ull gi = gs ? rx[lp]     : a0[lp];
                ull gf = gs ? rx[4 + lp] : a1[lp];
                ull gg = gs ? a0[4 + lp] : rx[lp];
                ull go = gs ? a1[4 + lp] : rx[4 + lp];
                float2 vi = unpk(gi), vf = unpk(gf), vg = unpk(gg), vo = unpk(go);
                float ncx = sig_a(vf.x) * cx[1][lp] + sig_a(vi.x) * tanh_a(vg.x);
                float ncy = sig_a(vf.y) * cy[1][lp] + sig_a(vi.y) * tanh_a(vg.y);
                cx[1][lp] = ncx; cy[1][lp] = ncy;
                float hx = sig_a(vo.x) * tanh_a(ncx);
                float hy = sig_a(vo.y) * tanh_a(ncy);
                if (!dup)
                    *(float2*)&h1w[j * TSTRIDE + r0 + 2 * (4 * gs + lp)] = make_float2(hx, hy);
            }
        }
        __syncthreads();   // h1 visible

        // ========= fc1+fc2 fused (4 rows per warp-task) + x for t+1 =========
        float f0 = 0.0f, f1 = 0.0f, f2 = 0.0f;
        const bool has_next = (t + 1 < TSTEPS);
        if (has_next) {
            int r = tid >> 4, s = tid & 15;
            f0 = fbase[(size_t)r * (TSTEPS * SDIM) + (size_t)(t + 1) * SDIM + s];
            int i1 = tid + NTHREADS;
            f1 = fbase[(size_t)(i1 >> 4) * (TSTEPS * SDIM) + (size_t)(t + 1) * SDIM + (i1 & 15)];
            if (tid < 1024 - 2 * NTHREADS) {
                int i2 = tid + 2 * NTHREADS;
                f2 = fbase[(size_t)(i2 >> 4) * (TSTEPS * SDIM) + (size_t)(t + 1) * SDIM + (i2 & 15)];
            }
        }

        // 16 quad-row tasks over 13 warps
        #pragma unroll
        for (int task = 0; task < 2; task++) {
            int dt = w + 13 * task;
            if (dt < 16) {
                int rb = dt * 4;
                ull acc0 = 0ULL, acc1 = 0ULL;
                if (lane < FC1N) {
                    float bb1 = s_bfc1[lane];
                    acc0 = pack2(bb1, bb1); acc1 = acc0;
                    const float* wr = &s_fc1[lane * FC1_S];
                    #pragma unroll 10
                    for (int k = 0; k < HID; k++) {
                        float wv = wr[k];
                        ull wp = pack2(wv, wv);
                        ulonglong2 hv = *(const ulonglong2*)&h1w[k * TSTRIDE + rb];
                        fma2(acc0, wp, hv.x);
                        fma2(acc1, wp, hv.y);
                    }
                    float2 u0 = unpk(acc0), u1 = unpk(acc1);
                    float sc = s_fc2[lane];
                    u0.x = fmaxf(u0.x, 0.0f) * sc;  u0.y = fmaxf(u0.y, 0.0f) * sc;
                    u1.x = fmaxf(u1.x, 0.0f) * sc;  u1.y = fmaxf(u1.y, 0.0f) * sc;
                    acc0 = pack2(u0.x, u0.y); acc1 = pack2(u1.x, u1.y);
                }
                #pragma unroll
                for (int off = 16; off > 0; off >>= 1) {
                    add2(acc0, __shfl_down_sync(0xffffffffu, acc0, off));
                    add2(acc1, __shfl_down_sync(0xffffffffu, acc1, off));
                }
                if (lane == 0) {
                    float2 d0 = unpk(acc0), d1 = unpk(acc1);
                    float bb = s_bfc2[0];
                    d0.x += bb; d0.y += bb; d1.x += bb; d1.y += bb;
                    float4 dd; dd.x = d0.x; dd.y = d0.y; dd.z = d1.x; dd.w = d1.y;
                    *(float4*)&s_x[SDIM * TSTRIDE + rb] = dd;   // delta -> next x
                    out[(size_t)(brow + rb)     * TSTEPS + t] = d0.x;
                    out[(size_t)(brow + rb + 1) * TSTEPS + t] = d0.y;
                    out[(size_t)(brow + rb + 2) * TSTEPS + t] = d1.x;
                    out[(size_t)(brow + rb + 3) * TSTEPS + t] = d1.y;
                }
            }
        }

        // store prefetched features for t+1
        if (has_next) {
            int r = tid >> 4, s = tid & 15;
            s_x[s * TSTRIDE + r] = f0;
            int i1 = tid + NTHREADS;
            s_x[(i1 & 15) * TSTRIDE + (i1 >> 4)] = f1;
            if (tid < 1024 - 2 * NTHREADS) {
                int i2 = tid + 2 * NTHREADS;
                s_x[(i2 & 15) * TSTRIDE + (i2 >> 4)] = f2;
            }
        }
        __syncthreads();   // delta + x(t+1) visible
    }
}

extern "C" void kernel_launch(void* const* d_in, const int* in_sizes, int n_in,
                              void* d_out, int out_size)
{
    const float* features = (const float*)d_in[0];
    const float* w_ih0    = (const float*)d_in[1];
    const float* w_hh0    = (const float*)d_in[2];
    const float* b0       = (const float*)d_in[3];
    const float* w_ih1    = (const float*)d_in[4];
    const float* w_hh1    = (const float*)d_in[5];
    const float* b1       = (const float*)d_in[6];
    const float* w_fc1    = (const float*)d_in[7];
    const float* b_fc1    = (const float*)d_in[8];
    const float* w_fc2    = (const float*)d_in[9];
    const float* b_fc2    = (const float*)d_in[10];
    float* out = (float*)d_out;

    const int batch = in_sizes[0] / (TSTEPS * SDIM);
    const int nblocks = batch / ROWS;

    const size_t smem_bytes = SMEM_FLOATS * sizeof(float);
    cudaFuncSetAttribute(kozyra_lstm_kernel,
                         cudaFuncAttributeMaxDynamicSharedMemorySize,
                         (int)smem_bytes);

    kozyra_lstm_kernel<<<nblocks, NTHREADS, smem_bytes>>>(
        features, w_ih0, w_hh0, b0, w_ih1, w_hh1, b1,
        w_fc1, b_fc1, w_fc2, b_fc2, out);
}

// round 7
// speedup vs baseline: 1.1002x; 1.1002x over previous
#include <cuda_runtime.h>

// Problem constants
#define HID     50
#define NG      200
#define IN0     17
#define SDIM    16
#define TSTEPS  128
#define FC1N    25

// Tiling: two independent 32-row halves, 13 warps each
#define ROWS      64
#define HROWS     32
#define NTHREADS  832     // 26 warps
#define HTHREADS  416     // per half
#define NPAIR     4       // 8 rows per slot

// Strides (floats)
#define WI_S      17
#define WH_S      51
#define FC1_S     51
#define TSTRIDE   68      // 272B rows, 16B-aligned

// Per-gate weight blocks; deltas == 16 (mod 32) banks -> half-warp complement
#define GB0       880
#define GBH       2576

typedef unsigned long long ull;

__device__ __forceinline__ ull pack2(float a, float b) {
    ull r; asm("mov.b64 %0,{%1,%2};" : "=l"(r) : "f"(a), "f"(b)); return r;
}
__device__ __forceinline__ float2 unpk(ull v) {
    float2 f; asm("mov.b64 {%0,%1},%2;" : "=f"(f.x), "=f"(f.y) : "l"(v)); return f;
}
__device__ __forceinline__ void fma2(ull& d, ull a, ull b) {
    asm("fma.rn.f32x2 %0,%1,%2,%0;" : "+l"(d) : "l"(a), "l"(b));
}
__device__ __forceinline__ void add2(ull& d, ull a) {
    asm("add.rn.f32x2 %0,%0,%1;" : "+l"(d) : "l"(a));
}
__device__ __forceinline__ float tanh_a(float x) {
    float y; asm("tanh.approx.f32 %0,%1;" : "=f"(y) : "f"(x)); return y;
}
__device__ __forceinline__ float sig_a(float x) {
    return fmaf(tanh_a(0.5f * x), 0.5f, 0.5f);
}
__device__ __forceinline__ void half_bar(int half) {
    asm volatile("bar.sync %0, %1;" :: "r"(half + 1), "r"(HTHREADS) : "memory");
}

// Shared layout (float offsets)
#define OFF_WIH0   0                       // 4*880  = 3520
#define OFF_WHH0   3520                    // 4*2576 = 10304
#define OFF_WIH1   13824
#define OFF_WHH1   24128
#define OFF_FC1    34432                   // 25*51 = 1275
#define OFF_FC2    35708                   // 25
#define OFF_B0     35734                   // 200
#define OFF_B1     35934                   // 200
#define OFF_BFC1   36134                   // 25
#define OFF_BFC2   36160                   // 2 (+2 pad)
#define OFF_X      36164                   // 17*68 = 1156
#define OFF_H0     37320                   // 2*50*68 = 6800
#define OFF_H1     44120                   // 6800
#define SMEM_FLOATS 50920                  // 203680 bytes

__global__ __launch_bounds__(NTHREADS, 1)
void kozyra_lstm_kernel(const float* __restrict__ features,
                        const float* __restrict__ w_ih0, const float* __restrict__ w_hh0,
                        const float* __restrict__ b0,
                        const float* __restrict__ w_ih1, const float* __restrict__ w_hh1,
                        const float* __restrict__ b1,
                        const float* __restrict__ w_fc1, const float* __restrict__ b_fc1,
                        const float* __restrict__ w_fc2, const float* __restrict__ b_fc2,
                        float* __restrict__ out)
{
    extern __shared__ float sm[];
    float* s_fc1  = sm + OFF_FC1;
    float* s_fc2  = sm + OFF_FC2;
    float* s_b0   = sm + OFF_B0;
    float* s_b1   = sm + OFF_B1;
    float* s_bfc1 = sm + OFF_BFC1;
    float* s_bfc2 = sm + OFF_BFC2;
    float* s_x    = sm + OFF_X;      // [IN0][TSTRIDE]
    float* s_h0b  = sm + OFF_H0;     // 2 x [HID][TSTRIDE]
    float* s_h1b  = sm + OFF_H1;

    const int tid  = threadIdx.x;
    const int brow = blockIdx.x * ROWS;

    // ---- Stage weights: per-gate blocks, order I(0) G(1) F(2) O(3) ----
    for (int idx = tid; idx < NG * IN0; idx += NTHREADS) {
        int row = idx / IN0, k = idx % IN0;
        int gate = row / HID, jj = row % HID;
        int blk = (gate == 0) ? 0 : (gate == 1) ? 2 : (gate == 2) ? 1 : 3;
        sm[OFF_WIH0 + blk * GB0 + jj * WI_S + k] = w_ih0[idx];
    }
    for (int idx = tid; idx < NG * HID; idx += NTHREADS) {
        int row = idx / HID, k = idx % HID;
        int gate = row / HID, jj = row % HID;
        int blk = (gate == 0) ? 0 : (gate == 1) ? 2 : (gate == 2) ? 1 : 3;
        int o = blk * GBH + jj * WH_S + k;
        sm[OFF_WHH0 + o] = w_hh0[idx];
        sm[OFF_WIH1 + o] = w_ih1[idx];
        sm[OFF_WHH1 + o] = w_hh1[idx];
    }
    for (int i = tid; i < FC1N * HID; i += NTHREADS) {
        int n = i / HID, k = i % HID;
        s_fc1[n * FC1_S + k] = w_fc1[i];
    }
    for (int i = tid; i < FC1N; i += NTHREADS) { s_fc2[i] = w_fc2[i]; s_bfc1[i] = b_fc1[i]; }
    for (int i = tid; i < NG;   i += NTHREADS) { s_b0[i] = b0[i]; s_b1[i] = b1[i]; }
    if (tid == 0) s_bfc2[0] = b_fc2[0];

    // ---- Init state + x for t=0 ----
    for (int i = tid; i < 2 * HID * TSTRIDE; i += NTHREADS) { s_h0b[i] = 0.0f; s_h1b[i] = 0.0f; }
    const float* fbase = features + (size_t)brow * (TSTEPS * SDIM);
    for (int i = tid; i < ROWS * SDIM; i += NTHREADS) {
        int r = i >> 4, s = i & 15;
        s_x[s * TSTRIDE + r] = fbase[(size_t)r * (TSTEPS * SDIM) + s];
    }
    if (tid < ROWS) s_x[SDIM * TSTRIDE + tid] = 0.0f;
    __syncthreads();   // last full-block barrier

    // ---- Thread mapping: half (13 warps, 32 rows) / straddle-free warps ----
    const int w    = tid >> 5;
    const int lane = tid & 31;
    const int half = (w >= 13) ? 1 : 0;
    const int hw   = w - half * 13;
    const int gs   = lane >> 4;          // 0 -> (i,f), 1 -> (g,o)
    const int sub  = lane & 15;
    int rg, j; bool dup = false;
    if (hw < 12) { rg = hw / 3; j = (hw % 3) * 16 + sub; }
    else { int s8 = sub & 7; dup = (sub >= 8); rg = s8 >> 1; j = 48 + (s8 & 1); }
    const int r0 = half * HROWS + rg * 8;   // global row base for this slot

    const float* pA_ih0 = sm + OFF_WIH0 + gs * GB0 + j * WI_S;
    const float* pB_ih0 = pA_ih0 + 2 * GB0;
    const float* pA_hh0 = sm + OFF_WHH0 + gs * GBH + j * WH_S;
    const float* pB_hh0 = pA_hh0 + 2 * GBH;
    const float* pA_ih1 = sm + OFF_WIH1 + gs * GBH + j * WH_S;
    const float* pB_ih1 = pA_ih1 + 2 * GBH;
    const float* pA_hh1 = sm + OFF_WHH1 + gs * GBH + j * WH_S;
    const float* pB_hh1 = pA_hh1 + 2 * GBH;

    const float bA0 = s_b0[(gs ? 2 : 0) * HID + j];
    const float bB0 = s_b0[(gs ? 3 : 1) * HID + j];
    const float bA1 = s_b1[(gs ? 2 : 0) * HID + j];
    const float bB1 = s_b1[(gs ? 3 : 1) * HID + j];
    const ull bpA0 = pack2(bA0, bA0), bpB0 = pack2(bB0, bB0);
    const ull bpA1 = pack2(bA1, bA1), bpB1 = pack2(bB1, bB1);

    float cx[2][2], cy[2][2];
    cx[0][0]=cx[0][1]=cy[0][0]=cy[0][1]=0.0f;
    cx[1][0]=cx[1][1]=cy[1][0]=cy[1][1]=0.0f;

    for (int t = 0; t < TSTEPS; t++) {
        const int pb = t & 1;
        float* h0r = s_h0b + pb * (HID * TSTRIDE);
        float* h0w = s_h0b + (pb ^ 1) * (HID * TSTRIDE);
        float* h1r = s_h1b + pb * (HID * TSTRIDE);
        float* h1w = s_h1b + (pb ^ 1) * (HID * TSTRIDE);

        ull a0[NPAIR], a1[NPAIR];

        // ================= Layer 0 =================
        #pragma unroll
        for (int p = 0; p < NPAIR; p++) { a0[p] = bpA0; a1[p] = bpB0; }

        #pragma unroll
        for (int k = 0; k < IN0; k++) {
            float wa = pA_ih0[k], wb = pB_ih0[k];
            ull wpa = pack2(wa, wa), wpb = pack2(wb, wb);
            ulonglong2 sv0 = *(const ulonglong2*)&s_x[k * TSTRIDE + r0];
            fma2(a0[0], wpa, sv0.x); fma2(a0[1], wpa, sv0.y);
            fma2(a1[0], wpb, sv0.x); fma2(a1[1], wpb, sv0.y);
            ulonglong2 sv1 = *(const ulonglong2*)&s_x[k * TSTRIDE + r0 + 4];
            fma2(a0[2], wpa, sv1.x); fma2(a0[3], wpa, sv1.y);
            fma2(a1[2], wpb, sv1.x); fma2(a1[3], wpb, sv1.y);
        }
        #pragma unroll 5
        for (int k = 0; k < HID; k++) {
            float wa = pA_hh0[k], wb = pB_hh0[k];
            ull wpa = pack2(wa, wa), wpb = pack2(wb, wb);
            ulonglong2 sv0 = *(const ulonglong2*)&h0r[k * TSTRIDE + r0];
            fma2(a0[0], wpa, sv0.x); fma2(a0[1], wpa, sv0.y);
            fma2(a1[0], wpb, sv0.x); fma2(a1[1], wpb, sv0.y);
            ulonglong2 sv1 = *(const ulonglong2*)&h0r[k * TSTRIDE + r0 + 4];
            fma2(a0[2], wpa, sv1.x); fma2(a0[3], wpa, sv1.y);
            fma2(a1[2], wpb, sv1.x); fma2(a1[3], wpb, sv1.y);
        }

        {   // exchange + nonlinearity, layer 0
            ull sx0 = gs ? a0[0] : a0[2];
            ull sx1 = gs ? a0[1] : a0[3];
            ull sx2 = gs ? a1[0] : a1[2];
            ull sx3 = gs ? a1[1] : a1[3];
            ull rx0 = __shfl_xor_sync(0xffffffffu, sx0, 16);
            ull rx1 = __shfl_xor_sync(0xffffffffu, sx1, 16);
            ull rx2 = __shfl_xor_sync(0xffffffffu, sx2, 16);
            ull rx3 = __shfl_xor_sync(0xffffffffu, sx3, 16);
            #pragma unroll
            for (int lp = 0; lp < 2; lp++) {
                ull gi = gs ? (lp ? rx1 : rx0) : a0[lp];
                ull gf = gs ? (lp ? rx3 : rx2) : a1[lp];
                ull gg = gs ? a0[2 + lp]       : (lp ? rx1 : rx0);
                ull go = gs ? a1[2 + lp]       : (lp ? rx3 : rx2);
                float2 vi = unpk(gi), vf = unpk(gf), vg = unpk(gg), vo = unpk(go);
                float ncx = sig_a(vf.x) * cx[0][lp] + sig_a(vi.x) * tanh_a(vg.x);
                float ncy = sig_a(vf.y) * cy[0][lp] + sig_a(vi.y) * tanh_a(vg.y);
                cx[0][lp] = ncx; cy[0][lp] = ncy;
                float hx = sig_a(vo.x) * tanh_a(ncx);
                float hy = sig_a(vo.y) * tanh_a(ncy);
                if (!dup)
                    *(float2*)&h0w[j * TSTRIDE + r0 + 2 * (2 * gs + lp)] = make_float2(hx, hy);
            }
        }
        half_bar(half);   // h0 (this half's rows) visible

        // ================= Layer 1 =================
        #pragma unroll
        for (int p = 0; p < NPAIR; p++) { a0[p] = bpA1; a1[p] = bpB1; }

        #pragma unroll 5
        for (int k = 0; k < HID; k++) {
            float wa = pA_ih1[k], wb = pB_ih1[k];
            ull wpa = pack2(wa, wa), wpb = pack2(wb, wb);
            ulonglong2 sv0 = *(const ulonglong2*)&h0w[k * TSTRIDE + r0];
            fma2(a0[0], wpa, sv0.x); fma2(a0[1], wpa, sv0.y);
            fma2(a1[0], wpb, sv0.x); fma2(a1[1], wpb, sv0.y);
            ulonglong2 sv1 = *(const ulonglong2*)&h0w[k * TSTRIDE + r0 + 4];
            fma2(a0[2], wpa, sv1.x); fma2(a0[3], wpa, sv1.y);
            fma2(a1[2], wpb, sv1.x); fma2(a1[3], wpb, sv1.y);
        }
        #pragma unroll 5
        for (int k = 0; k < HID; k++) {
            float wa = pA_hh1[k], wb = pB_hh1[k];
            ull wpa = pack2(wa, wa), wpb = pack2(wb, wb);
            ulonglong2 sv0 = *(const ulonglong2*)&h1r[k * TSTRIDE + r0];
            fma2(a0[0], wpa, sv0.x); fma2(a0[1], wpa, sv0.y);
            fma2(a1[0], wpb, sv0.x); fma2(a1[1], wpb, sv0.y);
            ulonglong2 sv1 = *(const ulonglong2*)&h1r[k * TSTRIDE + r0 + 4];
            fma2(a0[2], wpa, sv1.x); fma2(a0[3], wpa, sv1.y);
            fma2(a1[2], wpb, sv1.x); fma2(a1[3], wpb, sv1.y);
        }

        {   // exchange + nonlinearity, layer 1
            ull sx0 = gs ? a0[0] : a0[2];
            ull sx1 = gs ? a0[1] : a0[3];
            ull sx2 = gs ? a1[0] : a1[2];
            ull sx3 = gs ? a1[1] : a1[3];
            ull rx0 = __shfl_xor_sync(0xffffffffu, sx0, 16);
            ull rx1 = __shfl_xor_sync(0xffffffffu, sx1, 16);
            ull rx2 = __shfl_xor_sync(0xffffffffu, sx2, 16);
            ull rx3 = __shfl_xor_sync(0xffffffffu, sx3, 16);
            #pragma unroll
            for (int lp = 0; lp < 2; lp++) {
                ull gi = gs ? (lp ? rx1 : rx0) : a0[lp];
                ull gf = gs ? (lp ? rx3 : rx2) : a1[lp];
                ull gg = gs ? a0[2 + lp]       : (lp ? rx1 : rx0);
                ull go = gs ? a1[2 + lp]       : (lp ? rx3 : rx2);
                float2 vi = unpk(gi), vf = unpk(gf), vg = unpk(gg), vo = unpk(go);
                float ncx = sig_a(vf.x) * cx[1][lp] + sig_a(vi.x) * tanh_a(vg.x);
                float ncy = sig_a(vf.y) * cy[1][lp] + sig_a(vi.y) * tanh_a(vg.y);
                cx[1][lp] = ncx; cy[1][lp] = ncy;
                float hx = sig_a(vo.x) * tanh_a(ncx);
                float hy = sig_a(vo.y) * tanh_a(ncy);
                if (!dup)
                    *(float2*)&h1w[j * TSTRIDE + r0 + 2 * (2 * gs + lp)] = make_float2(hx, hy);
            }
        }
        half_bar(half);   // h1 (this half's rows) visible

        // ========= fc1+fc2 fused (4 rows/warp) + x for t+1, per half =========
        const bool has_next = (t + 1 < TSTEPS);
        const int hbase = half * HROWS;
        // feature prefetch for this half's 32 rows (512 elements / 416 threads)
        int hidx = hw * 32 + lane;           // 0..415
        float f0 = 0.0f, f1 = 0.0f;
        int rA = hidx >> 4, sA = hidx & 15;              // rows 0..25
        int hidx2 = hidx + HTHREADS;
        int rB = hidx2 >> 4, sB = hidx2 & 15;            // rows 26..31 for hidx<96
        if (has_next) {
            f0 = fbase[(size_t)(hbase + rA) * (TSTEPS * SDIM) + (size_t)(t + 1) * SDIM + sA];
            if (rB < HROWS)
                f1 = fbase[(size_t)(hbase + rB) * (TSTEPS * SDIM) + (size_t)(t + 1) * SDIM + sB];
        }

        // 8 quad-row fc tasks over 13 warps (warps 8..12 skip)
        if (hw < 8) {
            int rb = hbase + hw * 4;
            ull acc0 = 0ULL, acc1 = 0ULL;
            if (lane < FC1N) {
                float bb1 = s_bfc1[lane];
                acc0 = pack2(bb1, bb1); acc1 = acc0;
                const float* wr = &s_fc1[lane * FC1_S];
                #pragma unroll 10
                for (int k = 0; k < HID; k++) {
                    float wv = wr[k];
                    ull wp = pack2(wv, wv);
                    ulonglong2 hv = *(const ulonglong2*)&h1w[k * TSTRIDE + rb];
                    fma2(acc0, wp, hv.x);
                    fma2(acc1, wp, hv.y);
                }
                float2 u0 = unpk(acc0), u1 = unpk(acc1);
                float sc = s_fc2[lane];
                u0.x = fmaxf(u0.x, 0.0f) * sc;  u0.y = fmaxf(u0.y, 0.0f) * sc;
                u1.x = fmaxf(u1.x, 0.0f) * sc;  u1.y = fmaxf(u1.y, 0.0f) * sc;
                acc0 = pack2(u0.x, u0.y); acc1 = pack2(u1.x, u1.y);
            }
            #pragma unroll
            for (int off = 16; off > 0; off >>= 1) {
                add2(acc0, __shfl_down_sync(0xffffffffu, acc0, off));
                add2(acc1, __shfl_down_sync(0xffffffffu, acc1, off));
            }
            if (lane == 0) {
                float2 d0 = unpk(acc0), d1 = unpk(acc1);
                float bb = s_bfc2[0];
                d0.x += bb; d0.y += bb; d1.x += bb; d1.y += bb;
                float4 dd; dd.x = d0.x; dd.y = d0.y; dd.z = d1.x; dd.w = d1.y;
                *(float4*)&s_x[SDIM * TSTRIDE + rb] = dd;   // delta -> next x
                out[(size_t)(brow + rb)     * TSTEPS + t] = d0.x;
                out[(size_t)(brow + rb + 1) * TSTEPS + t] = d0.y;
                out[(size_t)(brow + rb + 2) * TSTEPS + t] = d1.x;
                out[(size_t)(brow + rb + 3) * TSTEPS + t] = d1.y;
            }
        }

        // store prefetched features for t+1 (this half's rows)
        if (has_next) {
            s_x[sA * TSTRIDE + hbase + rA] = f0;
            if (rB < HROWS)
                s_x[sB * TSTRIDE + hbase + rB] = f1;
        }
        half_bar(half);   // delta + x(t+1) visible within half
    }
}

extern "C" void kernel_launch(void* const* d_in, const int* in_sizes, int n_in,
                              void* d_out, int out_size)
{
    const float* features = (const float*)d_in[0];
    const float* w_ih0    = (const float*)d_in[1];
    const float* w_hh0    = (const float*)d_in[2];
    const float* b0       = (const float*)d_in[3];
    const float* w_ih1    = (const float*)d_in[4];
    const float* w_hh1    = (const float*)d_in[5];
    const float* b1       = (const float*)d_in[6];
    const float* w_fc1    = (const float*)d_in[7];
    const float* b_fc1    = (const float*)d_in[8];
    const float* w_fc2    = (const float*)d_in[9];
    const float* b_fc2    = (const float*)d_in[10];
    float* out = (float*)d_out;

    const int batch = in_sizes[0] / (TSTEPS * SDIM);
    const int nblocks = batch / ROWS;

    const size_t smem_bytes = SMEM_FLOATS * sizeof(float);
    cudaFuncSetAttribute(kozyra_lstm_kernel,
                         cudaFuncAttributeMaxDynamicSharedMemorySize,
                         (int)smem_bytes);

    kozyra_lstm_kernel<<<nblocks, NTHREADS, smem_bytes>>>(
        features, w_ih0, w_hh0, b0, w_ih1, w_hh1, b1,
        w_fc1, b_fc1, w_fc2, b_fc2, out);
}